// round 9
// baseline (speedup 1.0000x reference)
#include <cuda_runtime.h>
#include <cstdint>

// Problem constants (fixed shapes from reference)
#define NUM_CLASSES 16
#define C_IN 21
#define D_HID 12      // 2*NUM_PARTS
#define P_OUT 7       // NUM_PARTS+1
#define BS 4
#define V 8
#define N_IMG (BS*V)  // 32
#define H 128
#define W 128
#define HW (H*W)      // 16384
#define EPS 1e-5f

#define PIX_PER_THREAD 4
#define THREADS 128
#define PIX_PER_BLOCK (THREADS * PIX_PER_THREAD)        // 512
#define BLOCKS_PER_IMG (HW / PIX_PER_BLOCK)             // 32
#define GRID (N_IMG * BLOCKS_PER_IMG)                   // 1024

// Output layout: tuple (out, feats) flattened:
//   out:   (32, 7, 128, 128)  at offset 0
//   feats: (32, 21, 128, 128) after it
#define OUT_ELEMS ((size_t)N_IMG * P_OUT * HW)
#define FEATS_ELEMS ((size_t)N_IMG * C_IN * HW)

typedef unsigned long long u64;

// ---- packed f32x2 helpers (Blackwell FFMA2; ptxas never auto-fuses) ----
__device__ __forceinline__ u64 pack2(float a, float b) {
    u64 r;
    asm("mov.b64 %0, {%1, %2};" : "=l"(r) : "f"(a), "f"(b));
    return r;
}
__device__ __forceinline__ void unpack2(u64 v, float& a, float& b) {
    asm("mov.b64 {%0, %1}, %2;" : "=f"(a), "=f"(b) : "l"(v));
}
__device__ __forceinline__ u64 fma2(u64 a, u64 b, u64 c) {
    u64 d;
    asm("fma.rn.f32x2 %0, %1, %2, %3;" : "=l"(d) : "l"(a), "l"(b), "l"(c));
    return d;
}

// Compute-only kernel: NO feats stores (the copy engine handles feats).
__global__ __launch_bounds__(THREADS, 8)   // ~60 regs -> 8 blocks/SM, 32 warps
void mvpartseg_compute_kernel(const float* __restrict__ x,     // (32,21,128,128)
                              const int*   __restrict__ cls,   // (4,1)
                              const float* __restrict__ W1,    // (16,12,21)
                              const float* __restrict__ b1,    // (16,12)
                              const float* __restrict__ g1,    // (16,12)
                              const float* __restrict__ be1,   // (16,12)
                              const float* __restrict__ rm1,   // (16,12)
                              const float* __restrict__ rv1,   // (16,12)
                              const float* __restrict__ W2,    // (16,7,12)
                              const float* __restrict__ b2,    // (16,7)
                              float* __restrict__ out)
{
    __shared__ __align__(16) float sA1t[C_IN * D_HID];   // [c][d], BN-folded
    __shared__ __align__(16) float sA2[P_OUT * D_HID];   // [p][d]
    __shared__ float sc1[D_HID];
    __shared__ float sb2[P_OUT];
    __shared__ float sinv[D_HID];

    const int t = threadIdx.x;
    const int n = blockIdx.x / BLOCKS_PER_IMG;       // image (view-folded) index
    const int k = cls[n / V];                        // selected class head

    // Fold BN into conv1 params
    if (t < D_HID) {
        const int i = k * D_HID + t;
        float inv = g1[i] * rsqrtf(rv1[i] + EPS);
        sinv[t] = inv;
        sc1[t]  = b1[i] * inv + be1[i] - rm1[i] * inv;
    }
    if (t < P_OUT) sb2[t] = b2[k * P_OUT + t];
    __syncthreads();

    for (int i = t; i < C_IN * D_HID; i += THREADS) {
        int c = i / D_HID, d = i % D_HID;
        sA1t[i] = W1[k * D_HID * C_IN + d * C_IN + c] * sinv[d];
    }
    for (int i = t; i < P_OUT * D_HID; i += THREADS) {
        sA2[i] = W2[k * P_OUT * D_HID + i];
    }
    __syncthreads();

    const int pix = (blockIdx.x % BLOCKS_PER_IMG) * PIX_PER_BLOCK + t * PIX_PER_THREAD;
    const float* xin = x + (size_t)n * C_IN * HW + pix;

    // Layer-1 accumulators: 4 pixels = 2 packed f32x2 lanes per hidden unit
    u64 acc01[D_HID], acc23[D_HID];
#pragma unroll
    for (int d = 0; d < D_HID; d++) {
        u64 bp = pack2(sc1[d], sc1[d]);
        acc01[d] = bp;
        acc23[d] = bp;
    }

    // Stream channels: LDG.128 -> packed FFMA2 into accumulators.
#pragma unroll
    for (int c = 0; c < C_IN; c++) {
        const float4 xv = *(const float4*)(xin + (size_t)c * HW);
        const u64 x01 = pack2(xv.x, xv.y);
        const u64 x23 = pack2(xv.z, xv.w);
        const float4* wrow = (const float4*)&sA1t[c * D_HID];
#pragma unroll
        for (int q = 0; q < D_HID / 4; q++) {
            const float4 w = wrow[q];
            const u64 w0 = pack2(w.x, w.x);
            const u64 w1 = pack2(w.y, w.y);
            const u64 w2 = pack2(w.z, w.z);
            const u64 w3 = pack2(w.w, w.w);
            acc01[4*q+0] = fma2(w0, x01, acc01[4*q+0]);
            acc23[4*q+0] = fma2(w0, x23, acc23[4*q+0]);
            acc01[4*q+1] = fma2(w1, x01, acc01[4*q+1]);
            acc23[4*q+1] = fma2(w1, x23, acc23[4*q+1]);
            acc01[4*q+2] = fma2(w2, x01, acc01[4*q+2]);
            acc23[4*q+2] = fma2(w2, x23, acc23[4*q+2]);
            acc01[4*q+3] = fma2(w3, x01, acc01[4*q+3]);
            acc23[4*q+3] = fma2(w3, x23, acc23[4*q+3]);
        }
    }

    // Unpack + ReLU hidden -> scalar float4 per hidden unit
    float4 hv[D_HID];
#pragma unroll
    for (int d = 0; d < D_HID; d++) {
        float a, b, cc, dd;
        unpack2(acc01[d], a, b);
        unpack2(acc23[d], cc, dd);
        hv[d] = make_float4(fmaxf(a, 0.0f), fmaxf(b, 0.0f),
                            fmaxf(cc, 0.0f), fmaxf(dd, 0.0f));
    }

    // Layer 2 + final relu (max over masked classes == relu of selected head)
    const size_t out_base = (size_t)n * P_OUT * HW + pix;
#pragma unroll
    for (int p = 0; p < P_OUT; p++) {
        float bb = sb2[p];
        float4 o = make_float4(bb, bb, bb, bb);
#pragma unroll
        for (int d = 0; d < D_HID; d++) {
            const float w = sA2[p * D_HID + d];
            o.x = fmaf(w, hv[d].x, o.x);
            o.y = fmaf(w, hv[d].y, o.y);
            o.z = fmaf(w, hv[d].z, o.z);
            o.w = fmaf(w, hv[d].w, o.w);
        }
        o.x = fmaxf(o.x, 0.0f);
        o.y = fmaxf(o.y, 0.0f);
        o.z = fmaxf(o.z, 0.0f);
        o.w = fmaxf(o.w, 0.0f);
        __stcs((float4*)(out + out_base + (size_t)p * HW), o);
    }
}

// Fork/join resources for the parallel copy-engine branch. Created once on the
// first (uncaptured) correctness call; reused inside graph capture. No device
// memory is allocated by stream/event creation.
static cudaStream_t g_copy_stream = nullptr;
static cudaEvent_t  g_ev_fork = nullptr;
static cudaEvent_t  g_ev_join = nullptr;
static bool         g_fork_ok = false;

extern "C" void kernel_launch(void* const* d_in, const int* in_sizes, int n_in,
                              void* d_out, int out_size)
{
    const float* x   = (const float*)d_in[0];
    const int*   cls = (const int*)  d_in[1];
    const float* W1  = (const float*)d_in[2];
    const float* b1  = (const float*)d_in[3];
    const float* g1  = (const float*)d_in[4];
    const float* be1 = (const float*)d_in[5];
    const float* rm1 = (const float*)d_in[6];
    const float* rv1 = (const float*)d_in[7];
    const float* W2  = (const float*)d_in[8];
    const float* b2  = (const float*)d_in[9];
    float* out   = (float*)d_out;
    float* feats = out + OUT_ELEMS;

    if (!g_copy_stream) {
        bool ok = (cudaStreamCreateWithFlags(&g_copy_stream, cudaStreamNonBlocking) == cudaSuccess);
        ok = ok && (cudaEventCreateWithFlags(&g_ev_fork, cudaEventDisableTiming) == cudaSuccess);
        ok = ok && (cudaEventCreateWithFlags(&g_ev_join, cudaEventDisableTiming) == cudaSuccess);
        g_fork_ok = ok;
    }

    if (g_fork_ok) {
        // Fork: feats memcpy on the copy engine, parallel to the compute kernel.
        cudaEventRecord(g_ev_fork, 0);
        cudaStreamWaitEvent(g_copy_stream, g_ev_fork, 0);
        cudaMemcpyAsync(feats, x, FEATS_ELEMS * sizeof(float),
                        cudaMemcpyDeviceToDevice, g_copy_stream);

        mvpartseg_compute_kernel<<<GRID, THREADS>>>(x, cls, W1, b1, g1, be1,
                                                    rm1, rv1, W2, b2, out);

        // Join: main stream waits for the copy branch.
        cudaEventRecord(g_ev_join, g_copy_stream);
        cudaStreamWaitEvent(0, g_ev_join, 0);
    } else {
        // Fallback: serial copy + compute on the main stream.
        cudaMemcpyAsync(feats, x, FEATS_ELEMS * sizeof(float),
                        cudaMemcpyDeviceToDevice, 0);
        mvpartseg_compute_kernel<<<GRID, THREADS>>>(x, cls, W1, b1, g1, be1,
                                                    rm1, rv1, W2, b2, out);
    }
}

// round 10
// speedup vs baseline: 1.4247x; 1.4247x over previous
#include <cuda_runtime.h>
#include <cstdint>

// Problem constants (fixed shapes from reference)
#define NUM_CLASSES 16
#define C_IN 21
#define D_HID 12      // 2*NUM_PARTS
#define P_OUT 7       // NUM_PARTS+1
#define BS 4
#define V 8
#define N_IMG (BS*V)  // 32
#define H 128
#define W 128
#define HW (H*W)      // 16384
#define EPS 1e-5f

#define PIX_PER_THREAD 4
#define THREADS 128
#define PIX_PER_BLOCK (THREADS * PIX_PER_THREAD)        // 512
#define BLOCKS_PER_IMG (HW / PIX_PER_BLOCK)             // 32
#define GRID (N_IMG * BLOCKS_PER_IMG)                   // 1024

#define TILE_CH_BYTES (PIX_PER_BLOCK * 4)               // 2048 B per channel
#define TILE_BYTES (C_IN * TILE_CH_BYTES)               // 43008 B

// Output layout: tuple (out, feats) flattened:
//   out:   (32, 7, 128, 128)  at offset 0
//   feats: (32, 21, 128, 128) after it
#define OUT_ELEMS ((size_t)N_IMG * P_OUT * HW)

typedef unsigned long long u64;

// ---- packed f32x2 helpers (Blackwell FFMA2; ptxas never auto-fuses) ----
__device__ __forceinline__ u64 pack2(float a, float b) {
    u64 r;
    asm("mov.b64 %0, {%1, %2};" : "=l"(r) : "f"(a), "f"(b));
    return r;
}
__device__ __forceinline__ void unpack2(u64 v, float& a, float& b) {
    asm("mov.b64 {%0, %1}, %2;" : "=f"(a), "=f"(b) : "l"(v));
}
__device__ __forceinline__ u64 fma2(u64 a, u64 b, u64 c) {
    u64 d;
    asm("fma.rn.f32x2 %0, %1, %2, %3;" : "=l"(d) : "l"(a), "l"(b), "l"(c));
    return d;
}

__device__ __forceinline__ uint32_t smem_u32(const void* p) {
    uint32_t a;
    asm("{ .reg .u64 t; cvta.to.shared.u64 t, %1; cvt.u32.u64 %0, t; }"
        : "=r"(a) : "l"(p));
    return a;
}

__global__ __launch_bounds__(THREADS, 5)
void mvpartseg_tma_kernel(const float* __restrict__ x,     // (32,21,128,128)
                          const int*   __restrict__ cls,   // (4,1)
                          const float* __restrict__ W1,    // (16,12,21)
                          const float* __restrict__ b1,    // (16,12)
                          const float* __restrict__ g1,    // (16,12)
                          const float* __restrict__ be1,   // (16,12)
                          const float* __restrict__ rm1,   // (16,12)
                          const float* __restrict__ rv1,   // (16,12)
                          const float* __restrict__ W2,    // (16,7,12)
                          const float* __restrict__ b2,    // (16,7)
                          float* __restrict__ out)
{
    // Pixel tile (channel-major, 2048 B per channel), filled by TMA bulk load.
    __shared__ __align__(128) char tile[TILE_BYTES];
    __shared__ __align__(16) float sA1t[C_IN * D_HID];   // [c][d], BN-folded
    __shared__ __align__(16) float sA2[P_OUT * D_HID];   // [p][d]
    __shared__ float sc1[D_HID];
    __shared__ float sb2[P_OUT];
    __shared__ float sinv[D_HID];
    __shared__ __align__(8) u64 mbar;

    const int t = threadIdx.x;
    const int n = blockIdx.x / BLOCKS_PER_IMG;       // image (view-folded) index
    const int blk = blockIdx.x % BLOCKS_PER_IMG;
    const int k = cls[n / V];                        // selected class head

    const uint32_t mbar_a = smem_u32(&mbar);
    const uint32_t tile_a = smem_u32(tile);
    // Global base of this block's pixel tile (element offset)
    const float* gsrc = x + (size_t)n * C_IN * HW + blk * PIX_PER_BLOCK;
    float* gfeats = out + OUT_ELEMS + (size_t)n * C_IN * HW + blk * PIX_PER_BLOCK;

    // ---- mbarrier init + TMA bulk loads (one latency event per block) ----
    if (t == 0) {
        asm volatile("mbarrier.init.shared.b64 [%0], %1;"
                     :: "r"(mbar_a), "r"(1) : "memory");
    }
    __syncthreads();
    if (t == 0) {
        asm volatile("mbarrier.arrive.expect_tx.shared.b64 _, [%0], %1;"
                     :: "r"(mbar_a), "r"((uint32_t)TILE_BYTES) : "memory");
#pragma unroll
        for (int c = 0; c < C_IN; c++) {
            asm volatile(
                "cp.async.bulk.shared::cta.global.mbarrier::complete_tx::bytes "
                "[%0], [%1], %2, [%3];"
                :: "r"(tile_a + c * TILE_CH_BYTES),
                   "l"(gsrc + (size_t)c * HW),
                   "r"((uint32_t)TILE_CH_BYTES),
                   "r"(mbar_a)
                : "memory");
        }
    }

    // ---- overlap: fold BN + stage weights while TMA is in flight ----
    if (t < D_HID) {
        const int i = k * D_HID + t;
        float inv = g1[i] * rsqrtf(rv1[i] + EPS);
        sinv[t] = inv;
        sc1[t]  = b1[i] * inv + be1[i] - rm1[i] * inv;
    }
    if (t < P_OUT) sb2[t] = b2[k * P_OUT + t];
    __syncthreads();
    for (int i = t; i < C_IN * D_HID; i += THREADS) {
        int c = i / D_HID, d = i % D_HID;
        sA1t[i] = W1[k * D_HID * C_IN + d * C_IN + c] * sinv[d];
    }
    for (int i = t; i < P_OUT * D_HID; i += THREADS) {
        sA2[i] = W2[k * P_OUT * D_HID + i];
    }
    __syncthreads();

    // ---- wait for the tile (acquire) ----
    {
        uint32_t done;
        asm volatile(
            "{\n\t"
            ".reg .pred p;\n\t"
            "mbarrier.try_wait.parity.acquire.cta.shared::cta.b64 p, [%1], %2;\n\t"
            "selp.b32 %0, 1, 0, p;\n\t"
            "}"
            : "=r"(done) : "r"(mbar_a), "r"(0) : "memory");
        if (!done) {
            asm volatile(
                "{\n\t"
                ".reg .pred P1;\n\t"
                "WL_%=:\n\t"
                "mbarrier.try_wait.parity.acquire.cta.shared::cta.b64 P1, [%0], %1, 0x989680;\n\t"
                "@P1 bra.uni WD_%=;\n\t"
                "bra.uni WL_%=;\n\t"
                "WD_%=:\n\t"
                "}"
                :: "r"(mbar_a), "r"(0) : "memory");
        }
    }

    // ---- feats output: TMA bulk stores drain while the SM computes ----
    if (t == 0) {
#pragma unroll
        for (int c = 0; c < C_IN; c++) {
            asm volatile(
                "cp.async.bulk.global.shared::cta.bulk_group [%0], [%1], %2;"
                :: "l"(gfeats + (size_t)c * HW),
                   "r"(tile_a + c * TILE_CH_BYTES),
                   "r"((uint32_t)TILE_CH_BYTES)
                : "memory");
        }
        asm volatile("cp.async.bulk.commit_group;" ::: "memory");
    }

    // ---- compute from smem (LDS.128, 29-cyc latency, conflict-free) ----
    u64 acc01[D_HID], acc23[D_HID];
#pragma unroll
    for (int d = 0; d < D_HID; d++) {
        u64 bp = pack2(sc1[d], sc1[d]);
        acc01[d] = bp;
        acc23[d] = bp;
    }

    const char* my_tile = tile + t * (PIX_PER_THREAD * 4);
#pragma unroll
    for (int c = 0; c < C_IN; c++) {
        const float4 xv = *(const float4*)(my_tile + c * TILE_CH_BYTES);
        const u64 x01 = pack2(xv.x, xv.y);
        const u64 x23 = pack2(xv.z, xv.w);
        const float4* wrow = (const float4*)&sA1t[c * D_HID];
#pragma unroll
        for (int q = 0; q < D_HID / 4; q++) {
            const float4 w = wrow[q];
            const u64 w0 = pack2(w.x, w.x);
            const u64 w1 = pack2(w.y, w.y);
            const u64 w2 = pack2(w.z, w.z);
            const u64 w3 = pack2(w.w, w.w);
            acc01[4*q+0] = fma2(w0, x01, acc01[4*q+0]);
            acc23[4*q+0] = fma2(w0, x23, acc23[4*q+0]);
            acc01[4*q+1] = fma2(w1, x01, acc01[4*q+1]);
            acc23[4*q+1] = fma2(w1, x23, acc23[4*q+1]);
            acc01[4*q+2] = fma2(w2, x01, acc01[4*q+2]);
            acc23[4*q+2] = fma2(w2, x23, acc23[4*q+2]);
            acc01[4*q+3] = fma2(w3, x01, acc01[4*q+3]);
            acc23[4*q+3] = fma2(w3, x23, acc23[4*q+3]);
        }
    }

    // Unpack + ReLU hidden -> scalar float4 per hidden unit
    float4 hv[D_HID];
#pragma unroll
    for (int d = 0; d < D_HID; d++) {
        float a, b, cc, dd;
        unpack2(acc01[d], a, b);
        unpack2(acc23[d], cc, dd);
        hv[d] = make_float4(fmaxf(a, 0.0f), fmaxf(b, 0.0f),
                            fmaxf(cc, 0.0f), fmaxf(dd, 0.0f));
    }

    // Layer 2 + final relu (max over masked classes == relu of selected head)
    const size_t out_base = (size_t)n * P_OUT * HW + blk * PIX_PER_BLOCK
                          + t * PIX_PER_THREAD;
#pragma unroll
    for (int p = 0; p < P_OUT; p++) {
        float bb = sb2[p];
        float4 o = make_float4(bb, bb, bb, bb);
#pragma unroll
        for (int d = 0; d < D_HID; d++) {
            const float w = sA2[p * D_HID + d];
            o.x = fmaf(w, hv[d].x, o.x);
            o.y = fmaf(w, hv[d].y, o.y);
            o.z = fmaf(w, hv[d].z, o.z);
            o.w = fmaf(w, hv[d].w, o.w);
        }
        o.x = fmaxf(o.x, 0.0f);
        o.y = fmaxf(o.y, 0.0f);
        o.z = fmaxf(o.z, 0.0f);
        o.w = fmaxf(o.w, 0.0f);
        __stcs((float4*)(out + out_base + (size_t)p * HW), o);
    }

    // ---- drain bulk stores before CTA retires (smem must stay valid) ----
    __syncthreads();
    if (t == 0) {
        asm volatile("cp.async.bulk.wait_group 0;" ::: "memory");
        asm volatile("mbarrier.inval.shared.b64 [%0];" :: "r"(mbar_a) : "memory");
    }
}

extern "C" void kernel_launch(void* const* d_in, const int* in_sizes, int n_in,
                              void* d_out, int out_size)
{
    const float* x   = (const float*)d_in[0];
    const int*   cls = (const int*)  d_in[1];
    const float* W1  = (const float*)d_in[2];
    const float* b1  = (const float*)d_in[3];
    const float* g1  = (const float*)d_in[4];
    const float* be1 = (const float*)d_in[5];
    const float* rm1 = (const float*)d_in[6];
    const float* rv1 = (const float*)d_in[7];
    const float* W2  = (const float*)d_in[8];
    const float* b2  = (const float*)d_in[9];
    float* out = (float*)d_out;

    mvpartseg_tma_kernel<<<GRID, THREADS>>>(x, cls, W1, b1, g1, be1, rm1, rv1,
                                            W2, b2, out);
}